// round 8
// baseline (speedup 1.0000x reference)
#include <cuda_runtime.h>
#include <cuda_fp16.h>
#include <cstdint>

#define DI __device__ __forceinline__

namespace {

constexpr int kT = 28;
constexpr int kI = 28;
constexpr int kH = 128;
constexpr int kC = 10;
constexpr int WARPS = 4;
constexpr int THREADS = WARPS * 32;       // 128
constexpr int TILES = 32768 / 32;         // 1024 warp-tiles (m32)
constexpr int GRID = TILES / WARPS;       // 256
constexpr int XROW = kT * kI;             // 784

// SMEM: paired-B fragment tables (uint4 per lane per (kt, nt-pair))
constexpr unsigned OFF_W = 0;                   // [8kt][8ntp][32][16B] = 32768
constexpr unsigned OFF_U = 32768;               // [2kt][8ntp][32][16B] = 8192
constexpr unsigned OFF_V = 32768 + 8192;        // [8kt][1ntp][32][16B] = 4096
constexpr unsigned SMEM_TOTAL = OFF_V + 4096;   // 45056

// pack two fp32 -> fp16x2 (lo = a, hi = b)
DI unsigned packh(float a, float b) {
  unsigned d;
  asm("cvt.rn.f16x2.f32 %0, %1, %2;" : "=r"(d) : "f"(b), "f"(a));
  return d;
}
DI unsigned packh2(float2 v) { return packh(v.x, v.y); }

DI unsigned th2(unsigned h2) {  // tanh on fp16x2, one MUFU per 2 elems
  unsigned r;
  asm("tanh.approx.f16x2 %0, %1;" : "=r"(r) : "r"(h2));
  return r;
}

// C += A(m16k16 f16) * B(k16n8 f16), fp32 accumulate
DI void mma16(float* c, const unsigned* a, unsigned bx, unsigned by) {
  asm("mma.sync.aligned.m16n8k16.row.col.f32.f16.f16.f32 "
      "{%0,%1,%2,%3},{%4,%5,%6,%7},{%8,%9},{%0,%1,%2,%3};"
      : "+f"(c[0]), "+f"(c[1]), "+f"(c[2]), "+f"(c[3])
      : "r"(a[0]), "r"(a[1]), "r"(a[2]), "r"(a[3]), "r"(bx), "r"(by));
}
DI void mma16z(float* c, const unsigned* a, unsigned bx, unsigned by) {
  asm("mma.sync.aligned.m16n8k16.row.col.f32.f16.f16.f32 "
      "{%0,%1,%2,%3},{%4,%5,%6,%7},{%8,%9},{%10,%10,%10,%10};"
      : "=f"(c[0]), "=f"(c[1]), "=f"(c[2]), "=f"(c[3])
      : "r"(a[0]), "r"(a[1]), "r"(a[2]), "r"(a[3]), "r"(bx), "r"(by),
        "f"(0.0f));
}

// B element (n,k) -> byte offset; ntpn = nt-pairs per kt (W/U: 8, V: 1)
DI unsigned bpos(int n, int k, int ntpn) {
  int kt = k >> 4, kk = k & 15, nt = n >> 3, rr = n & 7;
  int ntp = nt >> 1, sel = nt & 1;
  int ln = rr * 4 + ((kk >> 1) & 3);
  return (unsigned)((((kt * ntpn + ntp) * 32 + ln) << 4) + sel * 8 +
                    ((kk >> 3) & 1) * 4 + (kk & 1) * 2);
}

__global__ void __launch_bounds__(THREADS, 2) rnn_kernel(
    const float* __restrict__ x, const float* __restrict__ Uw,
    const float* __restrict__ Ub, const float* __restrict__ Ww,
    const float* __restrict__ Wb, const float* __restrict__ Vw,
    const float* __restrict__ Vb, float* __restrict__ out) {
  extern __shared__ __align__(16) char sm[];
  const int tid = threadIdx.x;
  const int w = tid >> 5, lane = tid & 31;
  const int r = lane >> 2, q = lane & 3;

  // ---- fp16 paired-B fragment tables, biases folded into U col 28 ----
  for (int idx = tid; idx < kH * kH; idx += THREADS) {  // W^T[k][n] = Ww[n*128+k]
    int n = idx >> 7, k = idx & 127;
    *(__half*)(sm + OFF_W + bpos(n, k, 8)) = __float2half_rn(Ww[idx]);
  }
  for (int idx = tid; idx < kH * 32; idx += THREADS) {  // U^T padded K=32
    int n = idx >> 5, k = idx & 31;
    float v = (k < kI) ? Uw[n * kI + k] : ((k == kI) ? (Ub[n] + Wb[n]) : 0.0f);
    *(__half*)(sm + OFF_U + bpos(n, k, 8)) = __float2half_rn(v);
  }
  for (int idx = tid; idx < 16 * kH; idx += THREADS) {  // V^T padded N=16
    int n = idx >> 7, k = idx & 127;
    float v = (n < kC) ? Vw[n * kH + k] : 0.0f;
    *(__half*)(sm + OFF_V + bpos(n, k, 1)) = __float2half_rn(v);
  }
  __syncthreads();

  const int g = blockIdx.x * WARPS + w;  // warp-tile of 32 batch rows
  const float* xbase = x + (long)(g * 32 + r) * XROW;  // lane row base
  const uint4* Utab = (const uint4*)(sm + OFF_U) + lane;
  const uint4* Wtab = (const uint4*)(sm + OFF_W) + lane;

  // A-fragments of [x_t | 1 | 0pad] per m-tile; each reg = one float2, converted at load
  unsigned xf[2][2][4];
  {
    const unsigned cpad = (q == 2) ? 0x00003C00u : 0u;  // cols 28..31 = 1,0,0,0
    if (q >= 2) {
      xf[0][1][2] = cpad; xf[0][1][3] = cpad;
      xf[1][1][2] = cpad; xf[1][1][3] = cpad;
    }
  }
  auto ldxf = [&](int t) {
    const float* bp = xbase + t * kI + 2 * q;
#pragma unroll
    for (int m = 0; m < 2; m++) {
      const float* p0 = bp + m * 16 * XROW;
      const float* p1 = p0 + 8 * XROW;
      xf[m][0][0] = packh2(*(const float2*)(p0));
      xf[m][0][1] = packh2(*(const float2*)(p1));
      xf[m][0][2] = packh2(*(const float2*)(p0 + 8));
      xf[m][0][3] = packh2(*(const float2*)(p1 + 8));
      xf[m][1][0] = packh2(*(const float2*)(p0 + 16));
      xf[m][1][1] = packh2(*(const float2*)(p1 + 16));
      if (q < 2) {
        xf[m][1][2] = packh2(*(const float2*)(p0 + 24));
        xf[m][1][3] = packh2(*(const float2*)(p1 + 24));
      }
    }
  };
  ldxf(0);

  // State S fragments: lo = kt 0..3, hi = kt 4..7; 3-array ping-pong
  unsigned Alo[2][4][4], Ahi[2][4][4], Tmp[2][4][4];

  // One step: reads (inLo, inHi) as S_{t-1}; writes new lo half -> outLo,
  // new hi half -> inHi (safe: inHi dead after this step's W MMAs).
  auto step = [&](unsigned(&inLo)[2][4][4], unsigned(&inHi)[2][4][4],
                  unsigned(&outLo)[2][4][4], int t) {
    float C[2][8][4];
#pragma unroll
    for (int half = 0; half < 2; half++) {
      // U part: C = x_t @ U^T (+ biases); kt=0 initializes C
#pragma unroll
      for (int i2 = 0; i2 < 4; i2++) {
        uint4 b = Utab[(0 * 8 + half * 4 + i2) * 32];
#pragma unroll
        for (int m = 0; m < 2; m++) {
          mma16z(C[m][2 * i2], xf[m][0], b.x, b.y);
          mma16z(C[m][2 * i2 + 1], xf[m][0], b.z, b.w);
        }
      }
#pragma unroll
      for (int i2 = 0; i2 < 4; i2++) {
        uint4 b = Utab[(1 * 8 + half * 4 + i2) * 32];
#pragma unroll
        for (int m = 0; m < 2; m++) {
          mma16(C[m][2 * i2], xf[m][1], b.x, b.y);
          mma16(C[m][2 * i2 + 1], xf[m][1], b.z, b.w);
        }
      }
      // prefetch x_{t+1} into xf (dead after half-1 U part) under the W MMAs
      if (half == 1 && t + 1 < kT) ldxf(t + 1);
      // W part: C += S_{t-1} @ W^T (one LDS.128 feeds 4 MMAs)
      if (t > 0) {
#pragma unroll
        for (int kt = 0; kt < 8; kt++) {
#pragma unroll
          for (int i2 = 0; i2 < 4; i2++) {
            uint4 b = Wtab[(kt * 8 + half * 4 + i2) * 32];
#pragma unroll
            for (int m = 0; m < 2; m++) {
              const unsigned* a =
                  (kt < 4) ? inLo[m][kt] : inHi[m][kt - 4];
              mma16(C[m][2 * i2], a, b.x, b.y);
              mma16(C[m][2 * i2 + 1], a, b.z, b.w);
            }
          }
        }
      }
      // transform: S half = tanh(C) -> fp16 A fragments (lane-identical remap)
#pragma unroll
      for (int m = 0; m < 2; m++)
#pragma unroll
        for (int i2 = 0; i2 < 4; i2++) {
          unsigned* dst = (half == 0) ? outLo[m][i2] : inHi[m][i2];
          dst[0] = th2(packh(C[m][2 * i2][0], C[m][2 * i2][1]));
          dst[1] = th2(packh(C[m][2 * i2][2], C[m][2 * i2][3]));
          dst[2] = th2(packh(C[m][2 * i2 + 1][0], C[m][2 * i2 + 1][1]));
          dst[3] = th2(packh(C[m][2 * i2 + 1][2], C[m][2 * i2 + 1][3]));
        }
    }
  };

#pragma unroll 1
  for (int t = 0; t < kT; t += 2) {
    step(Alo, Ahi, Tmp, t);      // new S: (Tmp, Ahi)
    step(Tmp, Ahi, Alo, t + 1);  // new S: (Alo, Ahi)
  }

  // output: out = S @ V^T + V_b (N padded to 16 = one nt-pair, kt stride 32)
  const float vb0 = __ldg(Vb + 2 * q), vb1 = __ldg(Vb + 2 * q + 1);
  const float vb8 = __ldg(Vb + 8), vb9 = __ldg(Vb + 9);
#pragma unroll
  for (int m = 0; m < 2; m++) {
    float o0[4], o1[4];
    const uint4* bb = (const uint4*)(sm + OFF_V) + lane;
    uint4 b = bb[0];
    mma16z(o0, Alo[m][0], b.x, b.y);
    mma16z(o1, Alo[m][0], b.z, b.w);
#pragma unroll
    for (int kt = 1; kt < 8; kt++) {
      b = bb[kt * 32];
      const unsigned* a = (kt < 4) ? Alo[m][kt] : Ahi[m][kt - 4];
      mma16(o0, a, b.x, b.y);
      mma16(o1, a, b.z, b.w);
    }
    const int row0 = g * 32 + m * 16 + r;
    *(float2*)(out + row0 * kC + 2 * q) = make_float2(o0[0] + vb0, o0[1] + vb1);
    *(float2*)(out + (row0 + 8) * kC + 2 * q) =
        make_float2(o0[2] + vb0, o0[3] + vb1);
    if (q == 0) {
      *(float2*)(out + row0 * kC + 8) = make_float2(o1[0] + vb8, o1[1] + vb9);
      *(float2*)(out + (row0 + 8) * kC + 8) =
          make_float2(o1[2] + vb8, o1[3] + vb9);
    }
  }
}

}  // namespace

extern "C" void kernel_launch(void* const* d_in, const int* in_sizes, int n_in,
                              void* d_out, int out_size) {
  (void)in_sizes; (void)n_in; (void)out_size;
  cudaFuncSetAttribute(rnn_kernel, cudaFuncAttributeMaxDynamicSharedMemorySize,
                       SMEM_TOTAL);
  rnn_kernel<<<GRID, THREADS, SMEM_TOTAL>>>(
      (const float*)d_in[0], (const float*)d_in[1], (const float*)d_in[2],
      (const float*)d_in[3], (const float*)d_in[4], (const float*)d_in[5],
      (const float*)d_in[6], (float*)d_out);
}